// round 9
// baseline (speedup 1.0000x reference)
#include <cuda_runtime.h>
#include <math.h>

namespace {

typedef unsigned long long ull;

constexpr int T = 384;
constexpr int SLOTS = 12;     // 32 lanes * 12 = 384 steps

__device__ __forceinline__ ull fma2(ull a, ull b, ull c) {
    ull d; asm("fma.rn.f32x2 %0, %1, %2, %3;" : "=l"(d) : "l"(a), "l"(b), "l"(c));
    return d;
}
__device__ __forceinline__ ull add2(ull a, ull b) {
    ull d; asm("add.rn.f32x2 %0, %1, %2;" : "=l"(d) : "l"(a), "l"(b));
    return d;
}
__device__ __forceinline__ ull pk(float lo, float hi) {
    ull r; asm("mov.b64 %0, {%1, %2};" : "=l"(r) : "f"(lo), "f"(hi));
    return r;
}
__device__ __forceinline__ float2 upk(ull u) {
    float2 f; asm("mov.b64 {%0, %1}, %2;" : "=f"(f.x), "=f"(f.y) : "l"(u));
    return f;
}

// One warp = 2 neurons (A=.lo, B=.hi). Lane l owns NEGATED memory accumulators
// m[0..11] for steps 12l..12l+11. Per step: 1 packed shfl (memory), short
// V-chain Vn = af*V + (In + mem + nrst), 12 packed scatter FMAs (weights
// wr[12D + j - r]; zero-padded region self-masks past lanes). The reset term
// nrst for step n is computed from Vn at the end of step n-1 (off-chain).
__global__ void __launch_bounds__(32) flif_kernel(
    const float* __restrict__ I,     // [S, T]
    const float* __restrict__ W,     // [4999]
    float* __restrict__ out_spk,     // [S, T]
    float* __restrict__ out_trc)     // [S, T]
{
    // wr[idx], idx in [-383,383]: wr[idx<=0]=0, wr[idx>0]=W[4999-idx].
    // Stored duplicated (w,w) at scrambled slot u+(u>>2), u = idx+384.
    __shared__ float2 wrx[960];
    __shared__ __align__(16) ull sIn[T];   // COEF*(I-1.75) packed (A,B)
    __shared__ __align__(16) ull strc[T];  // packed V trace

    const int lane = threadIdx.x;
    const int g    = blockIdx.x;
    const int sA   = 2 * g, sB = 2 * g + 1;

    for (int u = lane; u < 768; u += 32) {
        int idx = u - 384;
        float v = (idx >= 1) ? W[4999 - idx] : 0.0f;
        wrx[u + (u >> 2)] = make_float2(v, v);
    }

    const float COEF = (float)(pow(0.1, 0.15) * tgamma(2.0 - 0.15) / 0.5);

    const float* IA = I + (size_t)sA * T;
    const float* IB = I + (size_t)sB * T;
    {
        const float4* ia = reinterpret_cast<const float4*>(IA);
        const float4* ib = reinterpret_cast<const float4*>(IB);
        #pragma unroll
        for (int q = 0; q < 3; ++q) {
            float4 a = ia[lane + 32 * q], b = ib[lane + 32 * q];
            int t = (lane + 32 * q) * 4;
            sIn[t + 0] = pk(COEF * (a.x - 1.75f), COEF * (b.x - 1.75f));
            sIn[t + 1] = pk(COEF * (a.y - 1.75f), COEF * (b.y - 1.75f));
            sIn[t + 2] = pk(COEF * (a.z - 1.75f), COEF * (b.z - 1.75f));
            sIn[t + 3] = pk(COEF * (a.w - 1.75f), COEF * (b.w - 1.75f));
        }
    }
    const float rawA1 = IA[1];   // raw inputs for the exact N==1 branch
    const float rawB1 = IB[1];
    __syncwarp();

    const float af = (float)(1.0 - (double)COEF * 0.025);   // 1 - COEF*GL
    const ull A2   = pk(af, af);
    const ull NEG1 = pk(-1.0f, -1.0f);

    const ull* wrxu = reinterpret_cast<const ull*>(wrx);

    ull m[SLOTS];
    #pragma unroll
    for (int r = 0; r < SLOTS; ++r) m[r] = 0ull;

    ull V    = 0ull;               // packed V (init 0,0)
    ull nrst = pk(-20.0f, -20.0f); // V=0 > -50 -> spike at step 0 guaranteed
    ull vhold = 0ull;

    #pragma unroll 1
    for (int l0 = 0; l0 < 32; ++l0) {
        const int ubase = SLOTS * (lane - l0) + 384;   // multiple of 4
        const int sbase = ubase + (ubase >> 2);
        const bool mine = (lane == l0);

        // All 23 weights wr[12*(lane-l0) + v], v in [-11,11] (0 for past lanes)
        ull wv[23];
        #pragma unroll
        for (int v = -11; v <= 11; ++v)
            wv[v + 11] = wrxu[sbase + (v + (v >> 2))];

        // Block inputs -> registers (broadcast LDS.128 x6, off-chain)
        ull In[SLOTS];
        {
            const ulonglong2* ip = reinterpret_cast<const ulonglong2*>(&sIn[SLOTS * l0]);
            #pragma unroll
            for (int q = 0; q < 6; ++q) { ulonglong2 p = ip[q]; In[2*q] = p.x; In[2*q+1] = p.y; }
        }

        #pragma unroll
        for (int r = 0; r < SLOTS; ++r) {
            // memory for step n = 12*l0 + r lives in lane l0's m[r] (negated)
            ull mem = __shfl_sync(0xffffffffu, m[r], l0);

            // off-chain sum; V-chain is a single fma
            ull s  = add2(In[r], mem);
            ull s2 = add2(s, nrst);
            ull Vn = fma2(A2, V, s2);     // = V + COEF*(-GL(V-VL)+I) - memory - reset

            if (l0 == 0) {                // first-block specials (uniform)
                if (r == 0) Vn = pk(-90.0f, -90.0f);   // -70 - reset(20), V0=0 spikes
                if (r == 1) {
                    float2 v = upk(V);    // V = -90, no spike -> no reset
                    Vn = pk(v.x + 0.005f * (rawA1 / 0.025f - v.x),
                            v.y + 0.005f * (rawB1 / 0.025f - v.y));
                }
            }

            ull nd = fma2(Vn, NEG1, V);   // NEGATED delta = V - Vn
            if (l0 == 0 && r == 0) nd = 0ull;          // delta_0 excluded

            // reset term for NEXT step (hangs off Vn, off the chain)
            float2 vn = upk(Vn);
            nrst = pk(vn.x > -50.0f ? -20.0f : 0.0f,
                      vn.y > -50.0f ? -20.0f : 0.0f);
            V = Vn;

            // owner captures trace pairwise (STS.128 every 2 steps)
            if (r & 1) {
                if (mine) {
                    ulonglong2 pr; pr.x = vhold; pr.y = Vn;
                    *reinterpret_cast<ulonglong2*>(&strc[SLOTS * l0 + r - 1]) = pr;
                }
            } else vhold = Vn;

            // apply delta to ALL owned slots: weight wr[12D + (j - r)]
            #pragma unroll
            for (int j = 0; j < SLOTS; ++j)
                m[j] = fma2(nd, wv[j - r + 11], m[j]);
        }
    }

    __syncwarp();

    // ---- outputs: spikes from stored trace (spike_n = V_{n-1} > -50), exact ----
    ull pv = (lane == 0) ? 0ull : strc[SLOTS * lane - 1];
    float2 p = upk(pv);
    float tA[SLOTS], tB[SLOTS], kA[SLOTS], kB[SLOTS];
    #pragma unroll
    for (int r = 0; r < SLOTS; ++r) {
        float2 c = upk(strc[SLOTS * lane + r]);
        tA[r] = c.x; tB[r] = c.y;
        kA[r] = (p.x > -50.0f) ? 1.0f : 0.0f;
        kB[r] = (p.y > -50.0f) ? 1.0f : 0.0f;
        p = c;
    }

    const int bo = lane * SLOTS;
    #pragma unroll
    for (int q = 0; q < 3; ++q) {
        reinterpret_cast<float4*>(out_spk + (size_t)sA * T + bo)[q] =
            make_float4(kA[4*q], kA[4*q+1], kA[4*q+2], kA[4*q+3]);
        reinterpret_cast<float4*>(out_spk + (size_t)sB * T + bo)[q] =
            make_float4(kB[4*q], kB[4*q+1], kB[4*q+2], kB[4*q+3]);
        reinterpret_cast<float4*>(out_trc + (size_t)sA * T + bo)[q] =
            make_float4(tA[4*q], tA[4*q+1], tA[4*q+2], tA[4*q+3]);
        reinterpret_cast<float4*>(out_trc + (size_t)sB * T + bo)[q] =
            make_float4(tB[4*q], tB[4*q+1], tB[4*q+2], tB[4*q+3]);
    }
}

} // namespace

extern "C" void kernel_launch(void* const* d_in, const int* in_sizes, int n_in,
                              void* d_out, int out_size) {
    const float* I = (const float*)d_in[0];     // [2048, 384]
    const float* W = (const float*)d_in[1];     // [4999]
    float* out = (float*)d_out;                 // [spk | trc]
    const int S = in_sizes[0] / T;              // 2048
    float* out_spk = out;
    float* out_trc = out + (size_t)S * T;
    flif_kernel<<<S / 2, 32>>>(I, W, out_spk, out_trc);
}

// round 10
// speedup vs baseline: 1.2333x; 1.2333x over previous
#include <cuda_runtime.h>
#include <math.h>

namespace {

typedef unsigned long long ull;

constexpr int T = 384;
constexpr int SLOTS = 12;     // 32 lanes * 12 = 384 steps

__device__ __forceinline__ ull fma2(ull a, ull b, ull c) {
    ull d; asm("fma.rn.f32x2 %0, %1, %2, %3;" : "=l"(d) : "l"(a), "l"(b), "l"(c));
    return d;
}
__device__ __forceinline__ ull add2(ull a, ull b) {
    ull d; asm("add.rn.f32x2 %0, %1, %2;" : "=l"(d) : "l"(a), "l"(b));
    return d;
}
__device__ __forceinline__ ull pk(float lo, float hi) {
    ull r; asm("mov.b64 %0, {%1, %2};" : "=l"(r) : "f"(lo), "f"(hi));
    return r;
}
__device__ __forceinline__ float2 upk(ull u) {
    float2 f; asm("mov.b64 {%0, %1}, %2;" : "=f"(f.x), "=f"(f.y) : "l"(u));
    return f;
}

// One warp = 2 neurons (A=.lo, B=.hi). Lane l owns NEGATED memory accumulators
// m[0..11] for steps 12l..12l+11. Per step: 1 packed shfl (memory), short
// V-update, 12 packed scatter FMAs (weights wr[12D + j - r]; zero-padded
// region self-masks past lanes). Block l0=0 is fully peeled so the main loop
// body is branch-free (no BSSY/BSYNC brackets in the hot path).
__global__ void __launch_bounds__(32) flif_kernel(
    const float* __restrict__ I,     // [S, T]
    const float* __restrict__ W,     // [4999]
    float* __restrict__ out_spk,     // [S, T]
    float* __restrict__ out_trc)     // [S, T]
{
    // wr[idx], idx in [-383,383]: wr[idx<=0]=0, wr[idx>0]=W[4999-idx].
    // Stored duplicated (w,w) at scrambled slot u+(u>>2), u = idx+384.
    __shared__ float2 wrx[960];
    __shared__ __align__(16) ull sIn[T];   // COEF*(I-1.75) packed (A,B)
    __shared__ __align__(16) ull strc[T];  // packed V trace

    const int lane = threadIdx.x;
    const int g    = blockIdx.x;
    const int sA   = 2 * g, sB = 2 * g + 1;

    for (int u = lane; u < 768; u += 32) {
        int idx = u - 384;
        float v = (idx >= 1) ? W[4999 - idx] : 0.0f;
        wrx[u + (u >> 2)] = make_float2(v, v);
    }

    const float COEF = (float)(pow(0.1, 0.15) * tgamma(2.0 - 0.15) / 0.5);

    const float* IA = I + (size_t)sA * T;
    const float* IB = I + (size_t)sB * T;
    {
        const float4* ia = reinterpret_cast<const float4*>(IA);
        const float4* ib = reinterpret_cast<const float4*>(IB);
        #pragma unroll
        for (int q = 0; q < 3; ++q) {
            float4 a = ia[lane + 32 * q], b = ib[lane + 32 * q];
            int t = (lane + 32 * q) * 4;
            sIn[t + 0] = pk(COEF * (a.x - 1.75f), COEF * (b.x - 1.75f));
            sIn[t + 1] = pk(COEF * (a.y - 1.75f), COEF * (b.y - 1.75f));
            sIn[t + 2] = pk(COEF * (a.z - 1.75f), COEF * (b.z - 1.75f));
            sIn[t + 3] = pk(COEF * (a.w - 1.75f), COEF * (b.w - 1.75f));
        }
    }
    const float rawA1 = IA[1];   // raw inputs for the exact N==1 branch
    const float rawB1 = IB[1];
    __syncwarp();

    const float af = (float)(1.0 - (double)COEF * 0.025);   // 1 - COEF*GL
    const ull A2   = pk(af, af);
    const ull NEG1 = pk(-1.0f, -1.0f);

    const ull* wrxu = reinterpret_cast<const ull*>(wrx);

    ull m[SLOTS];
    #pragma unroll
    for (int r = 0; r < SLOTS; ++r) m[r] = 0ull;

    ull V = 0ull;         // packed V (init 0,0)
    ull vhold = 0ull;

    // ================= PEELED BLOCK l0 = 0 =================
    {
        const int ubase = SLOTS * lane + 384;
        const int sbase = ubase + (ubase >> 2);
        const bool mine = (lane == 0);

        ull wv[23];
        #pragma unroll
        for (int v = -11; v <= 11; ++v)
            wv[v + 11] = wrxu[sbase + (v + (v >> 2))];

        ull In[SLOTS];
        {
            const ulonglong2* ip = reinterpret_cast<const ulonglong2*>(&sIn[0]);
            #pragma unroll
            for (int q = 0; q < 6; ++q) { ulonglong2 p = ip[q]; In[2*q] = p.x; In[2*q+1] = p.y; }
        }

        // ---- step 0: V_pre = -70, V0=0 spikes -> Vn = -90, delta excluded ----
        V = pk(-90.0f, -90.0f);
        vhold = V;
        // ---- step 1: N==1 branch, V=-90 (no spike, no reset) ----
        {
            float2 v = upk(V);
            ull Vn = pk(v.x + 0.005f * (rawA1 / 0.025f - v.x),
                        v.y + 0.005f * (rawB1 / 0.025f - v.y));
            ull nd = fma2(Vn, NEG1, V);
            if (mine) {
                ulonglong2 pr; pr.x = vhold; pr.y = Vn;
                *reinterpret_cast<ulonglong2*>(&strc[0]) = pr;
            }
            V = Vn;
            #pragma unroll
            for (int j = 0; j < SLOTS; ++j)
                m[j] = fma2(nd, wv[j - 1 + 11], m[j]);
        }
        // ---- steps 2..11: normal ----
        #pragma unroll
        for (int r = 2; r < SLOTS; ++r) {
            ull mem = __shfl_sync(0xffffffffu, m[r], 0);
            float2 v = upk(V);
            ull nrst = pk(v.x > -50.0f ? -20.0f : 0.0f,
                          v.y > -50.0f ? -20.0f : 0.0f);
            ull Vq = fma2(A2, V, In[r]);
            ull Vp = add2(Vq, mem);
            ull Vn = add2(Vp, nrst);
            ull nd = fma2(Vn, NEG1, V);
            V = Vn;
            if (r & 1) {
                if (mine) {
                    ulonglong2 pr; pr.x = vhold; pr.y = Vn;
                    *reinterpret_cast<ulonglong2*>(&strc[r - 1]) = pr;
                }
            } else vhold = Vn;
            #pragma unroll
            for (int j = 0; j < SLOTS; ++j)
                m[j] = fma2(nd, wv[j - r + 11], m[j]);
        }
    }

    // ================= MAIN LOOP l0 = 1..31 (branch-free body) =================
    #pragma unroll 2
    for (int l0 = 1; l0 < 32; ++l0) {
        const int ubase = SLOTS * (lane - l0) + 384;   // multiple of 4
        const int sbase = ubase + (ubase >> 2);
        const bool mine = (lane == l0);

        // All 23 weights wr[12*(lane-l0) + v], v in [-11,11] (0 for past lanes)
        ull wv[23];
        #pragma unroll
        for (int v = -11; v <= 11; ++v)
            wv[v + 11] = wrxu[sbase + (v + (v >> 2))];

        // Block inputs -> registers (broadcast LDS.128 x6, off-chain)
        ull In[SLOTS];
        {
            const ulonglong2* ip = reinterpret_cast<const ulonglong2*>(&sIn[SLOTS * l0]);
            #pragma unroll
            for (int q = 0; q < 6; ++q) { ulonglong2 p = ip[q]; In[2*q] = p.x; In[2*q+1] = p.y; }
        }

        #pragma unroll
        for (int r = 0; r < SLOTS; ++r) {
            // memory for step n = 12*l0 + r lives in lane l0's m[r] (negated)
            ull mem = __shfl_sync(0xffffffffu, m[r], l0);

            float2 v = upk(V);
            ull nrst = pk(v.x > -50.0f ? -20.0f : 0.0f,
                          v.y > -50.0f ? -20.0f : 0.0f);

            ull Vq = fma2(A2, V, In[r]);          // (1-COEF*GL)*V + COEF*(I-1.75)
            ull Vp = add2(Vq, mem);               // + negated memory
            ull Vn = add2(Vp, nrst);              // detached reset
            ull nd = fma2(Vn, NEG1, V);           // NEGATED delta = V - Vn
            V = Vn;

            // owner captures trace pairwise (STS.128 every 2 steps)
            if (r & 1) {
                if (mine) {
                    ulonglong2 pr; pr.x = vhold; pr.y = Vn;
                    *reinterpret_cast<ulonglong2*>(&strc[SLOTS * l0 + r - 1]) = pr;
                }
            } else vhold = Vn;

            // apply delta to ALL owned slots: weight wr[12D + (j - r)]
            #pragma unroll
            for (int j = 0; j < SLOTS; ++j)
                m[j] = fma2(nd, wv[j - r + 11], m[j]);
        }
    }

    __syncwarp();

    // ---- outputs: spikes from stored trace (spike_n = V_{n-1} > -50), exact ----
    ull pv = (lane == 0) ? 0ull : strc[SLOTS * lane - 1];
    float2 p = upk(pv);
    float tA[SLOTS], tB[SLOTS], kA[SLOTS], kB[SLOTS];
    #pragma unroll
    for (int r = 0; r < SLOTS; ++r) {
        float2 c = upk(strc[SLOTS * lane + r]);
        tA[r] = c.x; tB[r] = c.y;
        kA[r] = (p.x > -50.0f) ? 1.0f : 0.0f;
        kB[r] = (p.y > -50.0f) ? 1.0f : 0.0f;
        p = c;
    }

    const int bo = lane * SLOTS;
    #pragma unroll
    for (int q = 0; q < 3; ++q) {
        reinterpret_cast<float4*>(out_spk + (size_t)sA * T + bo)[q] =
            make_float4(kA[4*q], kA[4*q+1], kA[4*q+2], kA[4*q+3]);
        reinterpret_cast<float4*>(out_spk + (size_t)sB * T + bo)[q] =
            make_float4(kB[4*q], kB[4*q+1], kB[4*q+2], kB[4*q+3]);
        reinterpret_cast<float4*>(out_trc + (size_t)sA * T + bo)[q] =
            make_float4(tA[4*q], tA[4*q+1], tA[4*q+2], tA[4*q+3]);
        reinterpret_cast<float4*>(out_trc + (size_t)sB * T + bo)[q] =
            make_float4(tB[4*q], tB[4*q+1], tB[4*q+2], tB[4*q+3]);
    }
}

} // namespace

extern "C" void kernel_launch(void* const* d_in, const int* in_sizes, int n_in,
                              void* d_out, int out_size) {
    const float* I = (const float*)d_in[0];     // [2048, 384]
    const float* W = (const float*)d_in[1];     // [4999]
    float* out = (float*)d_out;                 // [spk | trc]
    const int S = in_sizes[0] / T;              // 2048
    float* out_spk = out;
    float* out_trc = out + (size_t)S * T;
    flif_kernel<<<S / 2, 32>>>(I, W, out_spk, out_trc);
}